// round 5
// baseline (speedup 1.0000x reference)
#include <cuda_runtime.h>
#include <cstdint>

// Problem constants
#define N_      128
#define L_      1024
#define C_      512
#define LCAT_   2045                    // 1023 + 1022
#define INV_TEMP 14.285714285714285f    // 1 / 0.07

// Scratch: pred[l][m][c] for the current step (max Ls = 1023). 268 MB.
__device__ float g_pred[1023u * 128u * 512u];
__device__ unsigned int g_count[2];

// ---------------------------------------------------------------------------
// f32x2 packed helpers (sm_103a FFMA2 path — PTX-only, see SASS_QUICKREF)
// ---------------------------------------------------------------------------
__device__ __forceinline__ unsigned long long pack2(float lo, float hi) {
    unsigned long long r;
    asm("mov.b64 %0, {%1, %2};"
        : "=l"(r) : "r"(__float_as_uint(lo)), "r"(__float_as_uint(hi)));
    return r;
}
__device__ __forceinline__ void unpack2(unsigned long long v, float& lo, float& hi) {
    unsigned int a, b;
    asm("mov.b64 {%0, %1}, %2;" : "=r"(a), "=r"(b) : "l"(v));
    lo = __uint_as_float(a);
    hi = __uint_as_float(b);
}
__device__ __forceinline__ void ffma2(unsigned long long& d,
                                      unsigned long long a,
                                      unsigned long long b) {
    asm("fma.rn.f32x2 %0, %1, %2, %0;" : "+l"(d) : "l"(a), "l"(b));
}

// ---------------------------------------------------------------------------
// Kernel 1: pred[l][m][c] = sum_k P[m][l][k] * W[c][k] + b[c]
//   grid = (4 c-tiles, Ls),  block = 256, 128x128 tile, BK=16, 8x8/thread
// ---------------------------------------------------------------------------
__global__ __launch_bounds__(256, 2)
void pred_gemm(const float* __restrict__ P, const float* __restrict__ W,
               const float* __restrict__ bias, int step)
{
    const int l  = blockIdx.y;
    const int c0 = blockIdx.x * 128;

    __shared__ float As[16][128];   // As[k][m]
    __shared__ float Bs[16][128];   // Bs[k][c]

    const int tid = threadIdx.x;
    const int tx  = tid & 15;       // col group (c)
    const int ty  = tid >> 4;       // row group (m)

    unsigned long long acc[8][4];
#pragma unroll
    for (int i = 0; i < 8; i++)
#pragma unroll
        for (int j = 0; j < 4; j++) acc[i][j] = 0ull;

    const float* Abase = P + (size_t)l * C_;          // + m*(L_*C_) + k
    const float* Bbase = W + (size_t)c0 * C_;         // + c*C_ + k

    for (int k0 = 0; k0 < C_; k0 += 16) {
        // Load A tile (128 rows x 16) and B tile: 512 float4 each, 2/thread each
#pragma unroll
        for (int t = 0; t < 2; t++) {
            int e   = tid + t * 256;
            int row = e >> 2;
            int kq  = (e & 3) * 4;
            float4 va = *(const float4*)(Abase + (size_t)row * (L_ * C_) + k0 + kq);
            As[kq + 0][row] = va.x; As[kq + 1][row] = va.y;
            As[kq + 2][row] = va.z; As[kq + 3][row] = va.w;
            float4 vb = *(const float4*)(Bbase + (size_t)row * C_ + k0 + kq);
            Bs[kq + 0][row] = vb.x; Bs[kq + 1][row] = vb.y;
            Bs[kq + 2][row] = vb.z; Bs[kq + 3][row] = vb.w;
        }
        __syncthreads();
#pragma unroll
        for (int k = 0; k < 16; k++) {
            float a[8];
            *(float4*)&a[0] = *(const float4*)&As[k][ty * 8];
            *(float4*)&a[4] = *(const float4*)&As[k][ty * 8 + 4];
            unsigned long long b2[4];
            const unsigned long long* bp =
                (const unsigned long long*)&Bs[k][tx * 8];
            b2[0] = bp[0]; b2[1] = bp[1]; b2[2] = bp[2]; b2[3] = bp[3];
            unsigned long long a2[8];
#pragma unroll
            for (int i = 0; i < 8; i++) a2[i] = pack2(a[i], a[i]);
#pragma unroll
            for (int i = 0; i < 8; i++)
#pragma unroll
                for (int j = 0; j < 4; j++) ffma2(acc[i][j], a2[i], b2[j]);
        }
        __syncthreads();
    }

    // Epilogue: + bias, store pred[l][m][c]
    float bf[8];
#pragma unroll
    for (int j = 0; j < 8; j++) bf[j] = bias[c0 + tx * 8 + j];

    float* out = g_pred + (size_t)l * N_ * C_ + c0;
#pragma unroll
    for (int i = 0; i < 8; i++) {
        int m = ty * 8 + i;
        float v[8];
#pragma unroll
        for (int j = 0; j < 4; j++) unpack2(acc[i][j], v[2 * j], v[2 * j + 1]);
#pragma unroll
        for (int j = 0; j < 8; j++) v[j] += bf[j];
        *(float4*)(out + (size_t)m * C_ + tx * 8)     = make_float4(v[0], v[1], v[2], v[3]);
        *(float4*)(out + (size_t)m * C_ + tx * 8 + 4) = make_float4(v[4], v[5], v[6], v[7]);
    }
}

// ---------------------------------------------------------------------------
// Kernel 2: per-l 128x128 GEMM  l_neg[n][m] = sum_k T[n][l+step][k]*pred[l][m][k]
//   plus fused NCE accuracy count + scaled logits store.
//   grid = Ls, block = 256
// ---------------------------------------------------------------------------
__global__ __launch_bounds__(256, 2)
void lneg_gemm(const float* __restrict__ T, int step, int lofs, int cntIdx,
               float* __restrict__ outLogits)
{
    const int l = blockIdx.x;

    __shared__ float As[16][128];            // As[k][n]
    __shared__ float Bs[16][128];            // Bs[k][m]
    __shared__ float spos[N_];
    __shared__ unsigned int sflag[N_];

    const int tid = threadIdx.x;
    const int tx  = tid & 15;                // m group
    const int ty  = tid >> 4;                // n group

    unsigned long long acc[8][4];
#pragma unroll
    for (int i = 0; i < 8; i++)
#pragma unroll
        for (int j = 0; j < 4; j++) acc[i][j] = 0ull;

    const float* Abase = T + (size_t)(l + step) * C_;           // + n*(L_*C_) + k
    const float* Bbase = g_pred + (size_t)l * N_ * C_;          // + m*C_ + k

    for (int k0 = 0; k0 < C_; k0 += 16) {
#pragma unroll
        for (int t = 0; t < 2; t++) {
            int e   = tid + t * 256;
            int row = e >> 2;
            int kq  = (e & 3) * 4;
            float4 va = *(const float4*)(Abase + (size_t)row * (L_ * C_) + k0 + kq);
            As[kq + 0][row] = va.x; As[kq + 1][row] = va.y;
            As[kq + 2][row] = va.z; As[kq + 3][row] = va.w;
            float4 vb = *(const float4*)(Bbase + (size_t)row * C_ + k0 + kq);
            Bs[kq + 0][row] = vb.x; Bs[kq + 1][row] = vb.y;
            Bs[kq + 2][row] = vb.z; Bs[kq + 3][row] = vb.w;
        }
        __syncthreads();
#pragma unroll
        for (int k = 0; k < 16; k++) {
            float a[8];
            *(float4*)&a[0] = *(const float4*)&As[k][ty * 8];
            *(float4*)&a[4] = *(const float4*)&As[k][ty * 8 + 4];
            unsigned long long b2[4];
            const unsigned long long* bp =
                (const unsigned long long*)&Bs[k][tx * 8];
            b2[0] = bp[0]; b2[1] = bp[1]; b2[2] = bp[2]; b2[3] = bp[3];
            unsigned long long a2[8];
#pragma unroll
            for (int i = 0; i < 8; i++) a2[i] = pack2(a[i], a[i]);
#pragma unroll
            for (int i = 0; i < 8; i++)
#pragma unroll
                for (int j = 0; j < 4; j++) ffma2(acc[i][j], a2[i], b2[j]);
        }
        __syncthreads();
    }

    // Unpack raw l_neg values (unscaled, for the comparisons)
    float v[8][8];
#pragma unroll
    for (int i = 0; i < 8; i++)
#pragma unroll
        for (int j = 0; j < 4; j++) unpack2(acc[i][j], v[i][2 * j], v[i][2 * j + 1]);

    // Fused NCE accuracy: pos = l_neg[n][n]; row n succeeds iff pos > l_neg[n][m] for all m != n
    if (tid < N_) sflag[tid] = 1u;
    if (tx == ty) {
#pragma unroll
        for (int i = 0; i < 8; i++) spos[ty * 8 + i] = v[i][i];
    }
    __syncthreads();

#pragma unroll
    for (int i = 0; i < 8; i++) {
        const int n = ty * 8 + i;
        const float pos = spos[n];
        unsigned int ok = 1u;
#pragma unroll
        for (int j = 0; j < 8; j++) {
            const int m = tx * 8 + j;
            if (m != n) ok &= (pos > v[i][j]) ? 1u : 0u;
        }
        if (!ok) atomicAnd(&sflag[n], 0u);
    }
    __syncthreads();

    if (tid == 0) {
        unsigned int c = 0;
#pragma unroll 4
        for (int n = 0; n < N_; n++) c += sflag[n];
        atomicAdd(&g_count[cntIdx], c);
    }

    // Store scaled logits: out[n][m][lofs + l]
#pragma unroll
    for (int i = 0; i < 8; i++) {
        const size_t n = (size_t)(ty * 8 + i);
        float* rowp = outLogits + n * ((size_t)N_ * LCAT_) + (size_t)(lofs + l);
#pragma unroll
        for (int j = 0; j < 8; j++) {
            const size_t m = (size_t)(tx * 8 + j);
            rowp[m * LCAT_] = v[i][j] * INV_TEMP;
        }
    }
}

// ---------------------------------------------------------------------------
// Init: zero counters + fill y_trues region (as float)
// ---------------------------------------------------------------------------
__global__ void init_kernel(float* __restrict__ out)
{
    if (blockIdx.x == 0 && threadIdx.x < 2) g_count[threadIdx.x] = 0u;
    const size_t idx = (size_t)blockIdx.x * 256 + threadIdx.x;
    const size_t yN  = (size_t)N_ * LCAT_;
    if (idx < yN) {
        const size_t base = (size_t)N_ * N_ * LCAT_;
        out[base + idx] = (float)(idx / LCAT_);
    }
}

// ---------------------------------------------------------------------------
// Finalize: accs
// ---------------------------------------------------------------------------
__global__ void fin_kernel(float* __restrict__ out)
{
    if (threadIdx.x == 0) {
        const size_t base = (size_t)N_ * N_ * LCAT_ + (size_t)N_ * LCAT_;
        out[base + 0] = (float)g_count[0] / (float)(N_ * 1023);
        out[base + 1] = (float)g_count[1] / (float)(N_ * 1022);
    }
}

// ---------------------------------------------------------------------------
// Launch
// ---------------------------------------------------------------------------
extern "C" void kernel_launch(void* const* d_in, const int* in_sizes, int n_in,
                              void* d_out, int out_size)
{
    const float* ts = (const float*)d_in[0];   // timesteps         (N, L, C)
    const float* ps = (const float*)d_in[1];   // patient_timesteps (N, L, C)
    const float* W1 = (const float*)d_in[2];   // (C, C)
    const float* b1 = (const float*)d_in[3];   // (C,)
    const float* W2 = (const float*)d_in[4];   // (C, C)
    const float* b2 = (const float*)d_in[5];   // (C,)
    float* out = (float*)d_out;

    // y_trues + counter reset (261,760 elements)
    init_kernel<<<1023, 256>>>(out);

    // Step 1 (Ls = 1023), logits columns [0, 1023)
    {
        dim3 g(4, 1023);
        pred_gemm<<<g, 256>>>(ps, W1, b1, 1);
        lneg_gemm<<<1023, 256>>>(ts, 1, 0, 0, out);
    }
    // Step 2 (Ls = 1022), logits columns [1023, 2045)
    {
        dim3 g(4, 1022);
        pred_gemm<<<g, 256>>>(ps, W2, b2, 2);
        lneg_gemm<<<1022, 256>>>(ts, 2, 1023, 1, out);
    }

    fin_kernel<<<1, 32>>>(out);
}

// round 6
// speedup vs baseline: 1.2753x; 1.2753x over previous
#include <cuda_runtime.h>
#include <cstdint>

// Problem constants
#define N_      128
#define L_      1024
#define C_      512
#define LCAT_   2045                    // 1023 + 1022
#define INV_TEMP 14.285714285714285f    // 1 / 0.07

// Scratch: pred[l][m][c] for the current step (max Ls = 1023). 268 MB.
__device__ float g_pred[1023u * 128u * 512u];
__device__ unsigned int g_count[2];

// ---------------------------------------------------------------------------
// f32x2 packed helpers (sm_103a FFMA2 path — PTX-only)
// ---------------------------------------------------------------------------
__device__ __forceinline__ unsigned long long pack2(float lo, float hi) {
    unsigned long long r;
    asm("mov.b64 %0, {%1, %2};"
        : "=l"(r) : "r"(__float_as_uint(lo)), "r"(__float_as_uint(hi)));
    return r;
}
__device__ __forceinline__ void unpack2(unsigned long long v, float& lo, float& hi) {
    unsigned int a, b;
    asm("mov.b64 {%0, %1}, %2;" : "=r"(a), "=r"(b) : "l"(v));
    lo = __uint_as_float(a);
    hi = __uint_as_float(b);
}
__device__ __forceinline__ void ffma2(unsigned long long& d,
                                      unsigned long long a,
                                      unsigned long long b) {
    asm("fma.rn.f32x2 %0, %1, %2, %0;" : "+l"(d) : "l"(a), "l"(b));
}

// ---------------------------------------------------------------------------
// Shared inner machinery: 128x128x512 tile GEMM, BK=16, double-buffered.
// Thread tile 8x8 split as 2x2 chunks of 4x4:
//   rows  {ty*4 .. +3, 64+ty*4 .. +3},  cols {tx*4 .. +3, 64+tx*4 .. +3}
// B-fragment loads are LDS.128 over contiguous 16B chunks -> conflict-free.
// A-fragment loads broadcast within warp halves.
// ---------------------------------------------------------------------------
struct Frag { unsigned long long acc[8][4]; };

__device__ __forceinline__ void compute_tile(
    const float (*As)[128], const float (*Bs)[128],
    int tx, int ty, unsigned long long (&acc)[8][4])
{
#pragma unroll
    for (int k = 0; k < 16; k++) {
        float4 a0 = *(const float4*)&As[k][ty * 4];
        float4 a1 = *(const float4*)&As[k][64 + ty * 4];
        ulonglong2 bb0 = *(const ulonglong2*)&Bs[k][tx * 4];
        ulonglong2 bb1 = *(const ulonglong2*)&Bs[k][64 + tx * 4];
        unsigned long long b2[4] = { bb0.x, bb0.y, bb1.x, bb1.y };
        float af[8] = { a0.x, a0.y, a0.z, a0.w, a1.x, a1.y, a1.z, a1.w };
#pragma unroll
        for (int i = 0; i < 8; i++) {
            unsigned long long a2 = pack2(af[i], af[i]);
            ffma2(acc[i][0], a2, b2[0]);
            ffma2(acc[i][1], a2, b2[1]);
            ffma2(acc[i][2], a2, b2[2]);
            ffma2(acc[i][3], a2, b2[3]);
        }
    }
}

// ---------------------------------------------------------------------------
// Kernel 1: pred[l][m][c] = sum_k P[m][l][k] * W[c][k] + b[c]
//   grid = (4 c-tiles, Ls), block = 256
// ---------------------------------------------------------------------------
__global__ __launch_bounds__(256, 2)
void pred_gemm(const float* __restrict__ P, const float* __restrict__ W,
               const float* __restrict__ bias)
{
    const int l  = blockIdx.y;
    const int c0 = blockIdx.x * 128;

    __shared__ float As[2][16][128];
    __shared__ float Bs[2][16][128];

    const int tid = threadIdx.x;
    const int tx  = tid & 15;
    const int ty  = tid >> 4;

    unsigned long long acc[8][4];
#pragma unroll
    for (int i = 0; i < 8; i++)
#pragma unroll
        for (int j = 0; j < 4; j++) acc[i][j] = 0ull;

    const float* Abase = P + (size_t)l * C_;      // + m*(L_*C_) + k
    const float* Bbase = W + (size_t)c0 * C_;     // + c*C_ + k

    const int r0 = tid >> 2;            // 0..63
    const int r1 = 64 + r0;
    const int kq = (tid & 3) * 4;       // 0,4,8,12

    // Preload tile 0
    {
        float4 va0 = *(const float4*)(Abase + (size_t)r0 * (L_ * C_) + kq);
        float4 va1 = *(const float4*)(Abase + (size_t)r1 * (L_ * C_) + kq);
        float4 vb0 = *(const float4*)(Bbase + (size_t)r0 * C_ + kq);
        float4 vb1 = *(const float4*)(Bbase + (size_t)r1 * C_ + kq);
        As[0][kq+0][r0]=va0.x; As[0][kq+1][r0]=va0.y; As[0][kq+2][r0]=va0.z; As[0][kq+3][r0]=va0.w;
        As[0][kq+0][r1]=va1.x; As[0][kq+1][r1]=va1.y; As[0][kq+2][r1]=va1.z; As[0][kq+3][r1]=va1.w;
        Bs[0][kq+0][r0]=vb0.x; Bs[0][kq+1][r0]=vb0.y; Bs[0][kq+2][r0]=vb0.z; Bs[0][kq+3][r0]=vb0.w;
        Bs[0][kq+0][r1]=vb1.x; Bs[0][kq+1][r1]=vb1.y; Bs[0][kq+2][r1]=vb1.z; Bs[0][kq+3][r1]=vb1.w;
    }
    __syncthreads();

    int buf = 0;
    for (int k0 = 16; k0 < C_; k0 += 16) {
        // Prefetch next tile into registers
        float4 va0 = *(const float4*)(Abase + (size_t)r0 * (L_ * C_) + k0 + kq);
        float4 va1 = *(const float4*)(Abase + (size_t)r1 * (L_ * C_) + k0 + kq);
        float4 vb0 = *(const float4*)(Bbase + (size_t)r0 * C_ + k0 + kq);
        float4 vb1 = *(const float4*)(Bbase + (size_t)r1 * C_ + k0 + kq);

        compute_tile(As[buf], Bs[buf], tx, ty, acc);

        const int nb = buf ^ 1;
        As[nb][kq+0][r0]=va0.x; As[nb][kq+1][r0]=va0.y; As[nb][kq+2][r0]=va0.z; As[nb][kq+3][r0]=va0.w;
        As[nb][kq+0][r1]=va1.x; As[nb][kq+1][r1]=va1.y; As[nb][kq+2][r1]=va1.z; As[nb][kq+3][r1]=va1.w;
        Bs[nb][kq+0][r0]=vb0.x; Bs[nb][kq+1][r0]=vb0.y; Bs[nb][kq+2][r0]=vb0.z; Bs[nb][kq+3][r0]=vb0.w;
        Bs[nb][kq+0][r1]=vb1.x; Bs[nb][kq+1][r1]=vb1.y; Bs[nb][kq+2][r1]=vb1.z; Bs[nb][kq+3][r1]=vb1.w;
        __syncthreads();
        buf = nb;
    }
    compute_tile(As[buf], Bs[buf], tx, ty, acc);

    // Epilogue: + bias, store pred[l][m][c]
    float bf[8];
#pragma unroll
    for (int j = 0; j < 4; j++) {
        bf[j]     = bias[c0 + tx * 4 + j];
        bf[4 + j] = bias[c0 + 64 + tx * 4 + j];
    }

    float* out = g_pred + (size_t)l * N_ * C_ + c0;
#pragma unroll
    for (int i = 0; i < 8; i++) {
        const int m = (i < 4) ? (ty * 4 + i) : (64 + ty * 4 + (i - 4));
        float v[8];
#pragma unroll
        for (int j = 0; j < 4; j++) unpack2(acc[i][j], v[2 * j], v[2 * j + 1]);
#pragma unroll
        for (int j = 0; j < 8; j++) v[j] += bf[j];
        *(float4*)(out + (size_t)m * C_ + tx * 4)      = make_float4(v[0], v[1], v[2], v[3]);
        *(float4*)(out + (size_t)m * C_ + 64 + tx * 4) = make_float4(v[4], v[5], v[6], v[7]);
    }
}

// ---------------------------------------------------------------------------
// Kernel 2: per-l 128x128 GEMM  l_neg[n][m] = sum_k T[n][l+step][k]*pred[l][m][k]
//   + fused NCE accuracy count + scaled logits store. grid = Ls, block = 256
// ---------------------------------------------------------------------------
__global__ __launch_bounds__(256, 2)
void lneg_gemm(const float* __restrict__ T, int step, int lofs, int cntIdx,
               float* __restrict__ outLogits)
{
    const int l = blockIdx.x;

    __shared__ float As[2][16][128];
    __shared__ float Bs[2][16][128];
    __shared__ float spos[N_];
    __shared__ unsigned int sflag[N_];

    const int tid = threadIdx.x;
    const int tx  = tid & 15;
    const int ty  = tid >> 4;

    unsigned long long acc[8][4];
#pragma unroll
    for (int i = 0; i < 8; i++)
#pragma unroll
        for (int j = 0; j < 4; j++) acc[i][j] = 0ull;

    const float* Abase = T + (size_t)(l + step) * C_;       // + n*(L_*C_) + k
    const float* Bbase = g_pred + (size_t)l * N_ * C_;      // + m*C_ + k

    const int r0 = tid >> 2;
    const int r1 = 64 + r0;
    const int kq = (tid & 3) * 4;

    {
        float4 va0 = *(const float4*)(Abase + (size_t)r0 * (L_ * C_) + kq);
        float4 va1 = *(const float4*)(Abase + (size_t)r1 * (L_ * C_) + kq);
        float4 vb0 = *(const float4*)(Bbase + (size_t)r0 * C_ + kq);
        float4 vb1 = *(const float4*)(Bbase + (size_t)r1 * C_ + kq);
        As[0][kq+0][r0]=va0.x; As[0][kq+1][r0]=va0.y; As[0][kq+2][r0]=va0.z; As[0][kq+3][r0]=va0.w;
        As[0][kq+0][r1]=va1.x; As[0][kq+1][r1]=va1.y; As[0][kq+2][r1]=va1.z; As[0][kq+3][r1]=va1.w;
        Bs[0][kq+0][r0]=vb0.x; Bs[0][kq+1][r0]=vb0.y; Bs[0][kq+2][r0]=vb0.z; Bs[0][kq+3][r0]=vb0.w;
        Bs[0][kq+0][r1]=vb1.x; Bs[0][kq+1][r1]=vb1.y; Bs[0][kq+2][r1]=vb1.z; Bs[0][kq+3][r1]=vb1.w;
    }
    __syncthreads();

    int buf = 0;
    for (int k0 = 16; k0 < C_; k0 += 16) {
        float4 va0 = *(const float4*)(Abase + (size_t)r0 * (L_ * C_) + k0 + kq);
        float4 va1 = *(const float4*)(Abase + (size_t)r1 * (L_ * C_) + k0 + kq);
        float4 vb0 = *(const float4*)(Bbase + (size_t)r0 * C_ + k0 + kq);
        float4 vb1 = *(const float4*)(Bbase + (size_t)r1 * C_ + k0 + kq);

        compute_tile(As[buf], Bs[buf], tx, ty, acc);

        const int nb = buf ^ 1;
        As[nb][kq+0][r0]=va0.x; As[nb][kq+1][r0]=va0.y; As[nb][kq+2][r0]=va0.z; As[nb][kq+3][r0]=va0.w;
        As[nb][kq+0][r1]=va1.x; As[nb][kq+1][r1]=va1.y; As[nb][kq+2][r1]=va1.z; As[nb][kq+3][r1]=va1.w;
        Bs[nb][kq+0][r0]=vb0.x; Bs[nb][kq+1][r0]=vb0.y; Bs[nb][kq+2][r0]=vb0.z; Bs[nb][kq+3][r0]=vb0.w;
        Bs[nb][kq+0][r1]=vb1.x; Bs[nb][kq+1][r1]=vb1.y; Bs[nb][kq+2][r1]=vb1.z; Bs[nb][kq+3][r1]=vb1.w;
        __syncthreads();
        buf = nb;
    }
    compute_tile(As[buf], Bs[buf], tx, ty, acc);

    // Unpack raw l_neg values
    float v[8][8];
#pragma unroll
    for (int i = 0; i < 8; i++)
#pragma unroll
        for (int j = 0; j < 4; j++) unpack2(acc[i][j], v[i][2 * j], v[i][2 * j + 1]);

    // Row/col global indices for this thread's 8x8
    int rown[8], colm[8];
#pragma unroll
    for (int i = 0; i < 4; i++) {
        rown[i] = ty * 4 + i;      rown[4 + i] = 64 + ty * 4 + i;
        colm[i] = tx * 4 + i;      colm[4 + i] = 64 + tx * 4 + i;
    }

    // Fused NCE accuracy
    if (tid < N_) sflag[tid] = 1u;
    if (tx == ty) {
#pragma unroll
        for (int i = 0; i < 4; i++) {
            spos[ty * 4 + i]      = v[i][i];
            spos[64 + ty * 4 + i] = v[4 + i][4 + i];
        }
    }
    __syncthreads();

#pragma unroll
    for (int i = 0; i < 8; i++) {
        const int n = rown[i];
        const float pos = spos[n];
        unsigned int ok = 1u;
#pragma unroll
        for (int j = 0; j < 8; j++) {
            if (colm[j] != n) ok &= (pos > v[i][j]) ? 1u : 0u;
        }
        if (!ok) atomicAnd(&sflag[n], 0u);
    }
    __syncthreads();

    if (tid == 0) {
        unsigned int c = 0;
#pragma unroll 4
        for (int n = 0; n < N_; n++) c += sflag[n];
        atomicAdd(&g_count[cntIdx], c);
    }

    // Store scaled logits: out[n][m][lofs + l]
#pragma unroll
    for (int i = 0; i < 8; i++) {
        float* rowp = outLogits + (size_t)rown[i] * ((size_t)N_ * LCAT_)
                                + (size_t)(lofs + l);
#pragma unroll
        for (int j = 0; j < 8; j++) {
            rowp[(size_t)colm[j] * LCAT_] = v[i][j] * INV_TEMP;
        }
    }
}

// ---------------------------------------------------------------------------
// Init: zero counters + fill y_trues region (as float)
// ---------------------------------------------------------------------------
__global__ void init_kernel(float* __restrict__ out)
{
    if (blockIdx.x == 0 && threadIdx.x < 2) g_count[threadIdx.x] = 0u;
    const size_t idx = (size_t)blockIdx.x * 256 + threadIdx.x;
    const size_t yN  = (size_t)N_ * LCAT_;
    if (idx < yN) {
        const size_t base = (size_t)N_ * N_ * LCAT_;
        out[base + idx] = (float)(idx / LCAT_);
    }
}

// ---------------------------------------------------------------------------
// Finalize: accs
// ---------------------------------------------------------------------------
__global__ void fin_kernel(float* __restrict__ out)
{
    if (threadIdx.x == 0) {
        const size_t base = (size_t)N_ * N_ * LCAT_ + (size_t)N_ * LCAT_;
        out[base + 0] = (float)g_count[0] / (float)(N_ * 1023);
        out[base + 1] = (float)g_count[1] / (float)(N_ * 1022);
    }
}

// ---------------------------------------------------------------------------
// Launch
// ---------------------------------------------------------------------------
extern "C" void kernel_launch(void* const* d_in, const int* in_sizes, int n_in,
                              void* d_out, int out_size)
{
    const float* ts = (const float*)d_in[0];   // timesteps         (N, L, C)
    const float* ps = (const float*)d_in[1];   // patient_timesteps (N, L, C)
    const float* W1 = (const float*)d_in[2];   // (C, C)
    const float* b1 = (const float*)d_in[3];   // (C,)
    const float* W2 = (const float*)d_in[4];   // (C, C)
    const float* b2 = (const float*)d_in[5];   // (C,)
    float* out = (float*)d_out;

    init_kernel<<<1023, 256>>>(out);

    // Step 1 (Ls = 1023), logits columns [0, 1023)
    {
        dim3 g(4, 1023);
        pred_gemm<<<g, 256>>>(ps, W1, b1);
        lneg_gemm<<<1023, 256>>>(ts, 1, 0, 0, out);
    }
    // Step 2 (Ls = 1022), logits columns [1023, 2045)
    {
        dim3 g(4, 1022);
        pred_gemm<<<g, 256>>>(ps, W2, b2);
        lneg_gemm<<<1022, 256>>>(ts, 2, 1023, 1, out);
    }

    fin_kernel<<<1, 32>>>(out);
}